// round 1
// baseline (speedup 1.0000x reference)
#include <cuda_runtime.h>
#include <cuda_bf16.h>

// Kanvolution2d: out[b,o,h,w] = sum_k w_out[o,k] * P_ok(x_k) / (1 + |Q_ok(x_k)|)
// where x_k is the unfolded 3x3xC patch value, P is a cubic (4 coeffs), Q is
// x*(q1 + q2*x). B=4, C=16, H=W=32, O=32, K=144.
//
// FMA-issue-bound design:
//  - w_outer folded into P coefficients at shared-load time
//  - 4 output rows per thread (amortize broadcast weight LDS + x row cache)
//  - rcp.approx.f32 for the rational denominator (>=1, well conditioned)

#define C_IN 16
#define O_OUT 32
#define HW 32
#define KTOT 144           // C_IN * 9
#define TILE_ROWS 16
#define THREADS 128
#define XROWS (TILE_ROWS + 2)   // 18
#define XCOLS 34                // 32 + halo

__global__ __launch_bounds__(THREADS)
void kanvolution_kernel(const float* __restrict__ x,
                        const float* __restrict__ w_p,
                        const float* __restrict__ w_q,
                        const float* __restrict__ w_out,
                        float* __restrict__ out) {
    const int tile = blockIdx.x;     // 0..1 (row slab)
    const int o    = blockIdx.y;     // 0..31
    const int b    = blockIdx.z;     // 0..3
    const int r0   = tile * TILE_ROWS;
    const int tid  = threadIdx.x;

    __shared__ float s_x[C_IN][XROWS][XCOLS];
    __shared__ float s_wp[4][KTOT];  // w_out-folded P coefficients
    __shared__ float s_wq[2][KTOT];

    // --- stage weights (fold w_out into P) ---
    for (int k = tid; k < KTOT; k += THREADS) {
        float wo = w_out[o * KTOT + k];
        #pragma unroll
        for (int p = 0; p < 4; p++)
            s_wp[p][k] = wo * w_p[(o * 4 + p) * KTOT + k];
        s_wq[0][k] = w_q[(o * 2 + 0) * KTOT + k];
        s_wq[1][k] = w_q[(o * 2 + 1) * KTOT + k];
    }

    // --- zero halo columns (disjoint from interior writes below) ---
    for (int idx = tid; idx < C_IN * XROWS; idx += THREADS) {
        int c  = idx / XROWS;
        int rr = idx % XROWS;
        s_x[c][rr][0]  = 0.0f;
        s_x[c][rr][33] = 0.0f;
    }

    // --- stage x slab (rows r0-1 .. r0+16, zero for out-of-range) ---
    for (int idx = tid; idx < C_IN * XROWS * HW; idx += THREADS) {
        int w  = idx & 31;
        int t  = idx >> 5;
        int rr = t % XROWS;
        int c  = t / XROWS;
        int h  = r0 - 1 + rr;
        float v = 0.0f;
        if (h >= 0 && h < HW)
            v = x[((b * C_IN + c) * HW + h) * HW + w];
        s_x[c][rr][w + 1] = v;
    }
    __syncthreads();

    const int ow    = tid & 31;        // output column
    const int rbase = (tid >> 5) * 4;  // 4 rows per thread

    float acc[4] = {0.f, 0.f, 0.f, 0.f};

    for (int c = 0; c < C_IN; c++) {
        #pragma unroll
        for (int j = 0; j < 3; j++) {
            // cache the 6 x values (rows rbase..rbase+5) for this column tap
            float xv[6];
            #pragma unroll
            for (int rr = 0; rr < 6; rr++)
                xv[rr] = s_x[c][rbase + rr][ow + j];

            #pragma unroll
            for (int i = 0; i < 3; i++) {
                const int k = c * 9 + i * 3 + j;
                const float w0 = s_wp[0][k];
                const float w1 = s_wp[1][k];
                const float w2 = s_wp[2][k];
                const float w3 = s_wp[3][k];
                const float q1 = s_wq[0][k];
                const float q2 = s_wq[1][k];
                #pragma unroll
                for (int r = 0; r < 4; r++) {
                    const float xx = xv[r + i];
                    // summ_p (w_out folded in)
                    float sp = fmaf(fmaf(fmaf(w3, xx, w2), xx, w1), xx, w0);
                    // summ_q = q1*x + q2*x^2
                    float sq = fmaf(q2, xx, q1) * xx;
                    float den = 1.0f + fabsf(sq);
                    float rcp;
                    asm("rcp.approx.f32 %0, %1;" : "=f"(rcp) : "f"(den));
                    acc[r] = fmaf(sp, rcp, acc[r]);
                }
            }
        }
    }

    #pragma unroll
    for (int r = 0; r < 4; r++) {
        const int oh = r0 + rbase + r;
        out[((b * O_OUT + o) * HW + oh) * HW + ow] = acc[r];
    }
}

extern "C" void kernel_launch(void* const* d_in, const int* in_sizes, int n_in,
                              void* d_out, int out_size) {
    const float* x     = (const float*)d_in[0];  // [4,16,32,32]
    const float* w_p   = (const float*)d_in[1];  // [32,4,16,3,3]
    const float* w_q   = (const float*)d_in[2];  // [32,2,16,3,3]
    const float* w_out = (const float*)d_in[3];  // [32,16,3,3]
    float* out = (float*)d_out;                  // [4,32,32,32]

    dim3 grid(HW / TILE_ROWS, O_OUT, 4);  // (2, 32, 4) = 256 CTAs
    kanvolution_kernel<<<grid, THREADS>>>(x, w_p, w_q, w_out, out);
}